// round 5
// baseline (speedup 1.0000x reference)
#include <cuda_runtime.h>

// FwFM forward on GB300 — R5: scalar-lane layout to break the register wall.
// 16 lanes per sample (1 dim each), 2 samples/warp, 4 warps/block (8 samples),
// grid 1024. x[39] is 39 scalar regs instead of 78 packed -> ~2.3x occupancy.
// Pair weights live in smem row-padded to quads; one broadcast LDS.128 feeds
// 4 scalar FFMAs directly (no splat needed).

#define FIELDS 39
#define EDIM 16
#define BATCH 8192
#define SAMPLES_PER_BLOCK 8
#define THREADS 128
#define XPAD 42              // fields rounded up so padded quads stay in range
#define W2PAD 864            // >= sum of padded row lengths (798)

__global__ __launch_bounds__(THREADS, 7)   // caps regs at 73 -> 28 warps/SM
void fwfm_kernel(const int* __restrict__ inputs,
                 const float* __restrict__ emb,
                 const float* __restrict__ fw,
                 const float* __restrict__ lw,
                 const float* __restrict__ bias,
                 float* __restrict__ out)
{
    __shared__ __align__(16) float w2[W2PAD];   // row-padded pair weights
    __shared__ int idx_sh[SAMPLES_PER_BLOCK * FIELDS];

    const int tid = threadIdx.x;

    // Zero the padded weight array (pads must contribute 0).
    for (int k = tid; k < W2PAD; k += THREADS)
        w2[k] = 0.0f;
    __syncthreads();

    // Row i: len = 38-i weights from orig offset os(i) -> padded offset ps(i).
    {
        int os = 0, ps = 0;
        for (int i = 0; i < FIELDS - 1; i++) {
            const int len = FIELDS - 1 - i;
            for (int k = tid; k < len; k += THREADS)
                w2[ps + k] = fw[os + k];
            os += len;
            ps += (len + 3) & ~3;
        }
    }
    const int base = blockIdx.x * SAMPLES_PER_BLOCK * FIELDS;
    for (int k = tid; k < SAMPLES_PER_BLOCK * FIELDS; k += THREADS)
        idx_sh[k] = inputs[base + k];
    __syncthreads();

    const int warp = tid >> 5;
    const int lane = tid & 31;
    const int sub  = lane >> 4;       // sample within warp (0..1)
    const int d    = lane & 15;       // dim owned by this lane
    const int s_local = warp * 2 + sub;
    const int sample  = blockIdx.x * SAMPLES_PER_BLOCK + s_local;
    const int* my_idx = &idx_sh[s_local * FIELDS];

    // Gather: lane d loads dim d of each field. 16 lanes cover the 64B row.
    float x[XPAD];
#pragma unroll
    for (int f = 0; f < FIELDS; f++) {
        const int g = my_idx[f];
        x[f] = __ldg(emb + (size_t)g * EDIM + d);
    }
#pragma unroll
    for (int f = FIELDS; f < XPAD; f++)
        x[f] = 0.0f;                  // pad terms must be exactly 0

    // First-order partial: lane d covers fields d, d+16, d+32 (if present).
    float lin = lw[my_idx[d]] + lw[my_idx[d + 16]];
    if (d < FIELDS - 32) lin += lw[my_idx[d + 32]];

    // Second order: row i -> t = sum_{j>i} w * x[j]; acc += x[i]*t.
    // Weights consumed 4-at-a-time via one broadcast LDS.128; the four
    // components feed four independent accumulator chains.
    float acc = 0.0f;
    {
        int ps = 0;
#pragma unroll
        for (int i = 0; i < FIELDS - 1; i++) {
            const int len = FIELDS - 1 - i;
            const int nq  = (len + 3) >> 2;
            float t0 = 0.f, t1 = 0.f, t2 = 0.f, t3 = 0.f;
#pragma unroll
            for (int q = 0; q < nq; q++) {
                const float4 wq = *reinterpret_cast<const float4*>(&w2[ps + 4 * q]);
                const int j0 = i + 1 + 4 * q;
                t0 = fmaf(wq.x, x[j0 + 0], t0);
                t1 = fmaf(wq.y, x[j0 + 1], t1);
                t2 = fmaf(wq.z, x[j0 + 2], t2);
                t3 = fmaf(wq.w, x[j0 + 3], t3);
            }
            acc = fmaf(x[i], (t0 + t1) + (t2 + t3), acc);
            ps += nq << 2;
        }
    }

    float v = acc + lin;

    // Reduce across the 16 lanes of this sample (xor 8,4,2,1 stays in-group).
    v += __shfl_xor_sync(0xffffffffu, v, 8);
    v += __shfl_xor_sync(0xffffffffu, v, 4);
    v += __shfl_xor_sync(0xffffffffu, v, 2);
    v += __shfl_xor_sync(0xffffffffu, v, 1);

    if (d == 0)
        out[sample] = v + bias[0];
}

extern "C" void kernel_launch(void* const* d_in, const int* in_sizes, int n_in,
                              void* d_out, int out_size)
{
    const int*   inputs = (const int*)d_in[0];
    const float* emb    = (const float*)d_in[1];
    const float* fw     = (const float*)d_in[2];
    const float* lw     = (const float*)d_in[3];
    const float* bias   = (const float*)d_in[4];
    float*       out    = (float*)d_out;

    fwfm_kernel<<<BATCH / SAMPLES_PER_BLOCK, THREADS>>>(inputs, emb, fw, lw, bias, out);
}